// round 10
// baseline (speedup 1.0000x reference)
#include <cuda_runtime.h>
#include <cstdint>

// HadamardTransform: y[b,:,h,w] = (H_1024 @ pad(x[b,:,h,w]))[0:768] / 32
// FWHT-1024 per pixel, packed f32x2 (2 pixels/thread).
// Pass 1 (c_hi): ALL 24 loads issued first (preserve MLP), then H8 x3 +
//   H4xH8 recombine fused into the smem stores.   Peak 24 live u64.
// Pass 2 (c_lo): two sequential FWHT16 halves.     Peak 16 live u64.
// Low frame -> 4 CTAs/SM (32 warps) without spilling.

#define DIMC          768
#define TILE          16
#define THREADS       256
#define PIX_PER_IMG   3136
#define TILES_PER_IMG 196

// ---- packed f32x2 ops (sm_103a) ----
__device__ __forceinline__ uint64_t addx2(uint64_t a, uint64_t b) {
    uint64_t d; asm("add.rn.f32x2 %0, %1, %2;" : "=l"(d) : "l"(a), "l"(b)); return d;
}
__device__ __forceinline__ uint64_t subx2(uint64_t a, uint64_t b) {
    const uint64_t NEG1 = 0xBF800000BF800000ULL;   // (-1.0f, -1.0f)
    uint64_t d; asm("fma.rn.f32x2 %0, %1, %2, %3;" : "=l"(d) : "l"(b), "l"(NEG1), "l"(a)); return d;
}
__device__ __forceinline__ uint64_t mulx2(uint64_t a, uint64_t b) {
    uint64_t d; asm("mul.rn.f32x2 %0, %1, %2;" : "=l"(d) : "l"(a), "l"(b)); return d;
}

// smem layout (u64 units): row r (0..767) at (r + (r>>5))*8 + p2.
// Conflict-free 64-bit LDS/STS in both passes (32-row stride == 16 mod 32 banks).

__global__ __launch_bounds__(THREADS, 4)
void fwht1024_kernel(const float* __restrict__ x, float* __restrict__ y) {
    extern __shared__ uint64_t s[];   // 792*8 u64 = 50688 B

    const int tid = threadIdx.x;
    const int T   = blockIdx.x;
    const int b   = T / TILES_PER_IMG;
    const int p0  = (T % TILES_PER_IMG) * TILE;

    const int p2 = tid & 7;        // pixel pair -> pixels 2*p2, 2*p2+1
    const int g  = tid >> 3;       // 0..31

    const size_t base = (size_t)b * DIMC * PIX_PER_IMG + p0 + 2 * p2;

    // ---- Pass 1: FWHT32 over c_hi; 24 real inputs, 24 needed outputs ----
    {
        uint64_t w[24];
        // ALL loads first: 24 independent LDG.64 -> full MLP
        #pragma unroll
        for (int j = 0; j < 24; j++) {
            const float2 v = __ldcs((const float2*)(x + base +
                               (size_t)(j * 32 + g) * PIX_PER_IMG));
            uint64_t u;
            asm("mov.b64 %0, {%1, %2};" : "=l"(u) : "f"(v.x), "f"(v.y));
            w[j] = u;
        }

        // FWHT8 in place on each 8-block (bits 0..2 of j)
        #pragma unroll
        for (int blk = 0; blk < 3; blk++) {
            uint64_t* u = w + blk * 8;
            #pragma unroll
            for (int st = 0; st < 3; st++) {
                const int m = 1 << st;
                #pragma unroll
                for (int j = 0; j < 8; j++) {
                    if (!(j & m)) {
                        uint64_t a = u[j], c2 = u[j + m];
                        u[j]     = addx2(a, c2);
                        u[j + m] = subx2(a, c2);
                    }
                }
            }
        }

        // H4 (bits 3..4) recombine, fused into the stores:
        //   t[i]    = a'+b'+c'   (k_hi block 0)
        //   t[i+8]  = a'-b'+c'   (k_hi block 1)
        //   t[i+16] = a'+b'-c'   (k_hi block 2)     (blocks >= 24 discarded)
        #pragma unroll
        for (int i = 0; i < 8; i++) {
            uint64_t A = addx2(w[i], w[i + 8]);
            uint64_t B = subx2(w[i], w[i + 8]);
            s[((i     ) * 33 + g) * 8 + p2] = addx2(A, w[i + 16]);
            s[((i +  8) * 33 + g) * 8 + p2] = addx2(B, w[i + 16]);
            s[((i + 16) * 33 + g) * 8 + p2] = subx2(A, w[i + 16]);
        }
    }
    __syncthreads();

    // ---- Pass 2: FWHT32 over c_lo = stage m=16, then two FWHT16 halves ----
    if (g < 24) {
        const uint64_t SCALE = 0x3D0000003D000000ULL;   // (1/32, 1/32)
        const uint64_t* sr = s + (size_t)g * 33 * 8 + p2;

        #pragma unroll
        for (int half = 0; half < 2; half++) {
            uint64_t u[16];
            if (half == 0) {
                #pragma unroll
                for (int j = 0; j < 16; j++)
                    u[j] = addx2(sr[(size_t)j * 8], sr[(size_t)(j + 16) * 8]);
            } else {
                #pragma unroll
                for (int j = 0; j < 16; j++)
                    u[j] = subx2(sr[(size_t)j * 8], sr[(size_t)(j + 16) * 8]);
            }

            #pragma unroll
            for (int st = 0; st < 4; st++) {
                const int m = 1 << st;
                #pragma unroll
                for (int j = 0; j < 16; j++) {
                    if (!(j & m)) {
                        uint64_t a = u[j], c2 = u[j + m];
                        u[j]     = addx2(a, c2);
                        u[j + m] = subx2(a, c2);
                    }
                }
            }

            #pragma unroll
            for (int k = 0; k < 16; k++) {
                uint64_t r = mulx2(u[k], SCALE);
                float lo, hi;
                asm("mov.b64 {%0, %1}, %2;" : "=f"(lo), "=f"(hi) : "l"(r));
                __stcs((float2*)(y + base +
                        (size_t)(g * 32 + half * 16 + k) * PIX_PER_IMG),
                       make_float2(lo, hi));
            }
        }
    }
}

extern "C" void kernel_launch(void* const* d_in, const int* in_sizes, int n_in,
                              void* d_out, int out_size) {
    (void)in_sizes; (void)n_in; (void)out_size;
    const float* x = (const float*)d_in[0];
    float* y = (float*)d_out;

    const int smem_bytes = 792 * 8 * sizeof(uint64_t);   // 50688
    cudaFuncSetAttribute(fwht1024_kernel,
                         cudaFuncAttributeMaxDynamicSharedMemorySize, smem_bytes);

    const int grid = 16 * TILES_PER_IMG;   // 3136 tiles
    fwht1024_kernel<<<grid, THREADS, smem_bytes>>>(x, y);
}

// round 11
// speedup vs baseline: 1.4516x; 1.4516x over previous
#include <cuda_runtime.h>
#include <cstdint>

// HadamardTransform: y[b,:,h,w] = (H_1024 @ pad(x[b,:,h,w]))[0:768] / 32
// FWHT-1024 per pixel, packed f32x2 (2 pixels/thread), 3 CTAs/SM (uncapped).
// Pass 1 (c_hi): ALL 24 loads first (full MLP), FWHT8 x3, H4xH8 recombine
//                fused into the smem stores (no zero-pad registers).
// Pass 2 (c_lo): stage m=16 folded into smem reads; two sequential FWHT16
//                halves -> first 16 stores issue at the halfway point.

#define DIMC          768
#define TILE          16
#define THREADS       256
#define PIX_PER_IMG   3136
#define TILES_PER_IMG 196

// ---- packed f32x2 ops (sm_103a) ----
__device__ __forceinline__ uint64_t addx2(uint64_t a, uint64_t b) {
    uint64_t d; asm("add.rn.f32x2 %0, %1, %2;" : "=l"(d) : "l"(a), "l"(b)); return d;
}
__device__ __forceinline__ uint64_t subx2(uint64_t a, uint64_t b) {
    const uint64_t NEG1 = 0xBF800000BF800000ULL;   // (-1.0f, -1.0f)
    uint64_t d; asm("fma.rn.f32x2 %0, %1, %2, %3;" : "=l"(d) : "l"(b), "l"(NEG1), "l"(a)); return d;
}
__device__ __forceinline__ uint64_t mulx2(uint64_t a, uint64_t b) {
    uint64_t d; asm("mul.rn.f32x2 %0, %1, %2;" : "=l"(d) : "l"(a), "l"(b)); return d;
}

// smem layout (u64 units): row r (0..767) at (r + (r>>5))*8 + p2.
// Conflict-free 64-bit LDS/STS in both passes (32-row stride == 16 mod 32 banks).

__global__ __launch_bounds__(THREADS, 3)
void fwht1024_kernel(const float* __restrict__ x, float* __restrict__ y) {
    extern __shared__ uint64_t s[];   // 792*8 u64 = 50688 B

    const int tid = threadIdx.x;
    const int T   = blockIdx.x;
    const int b   = T / TILES_PER_IMG;
    const int p0  = (T % TILES_PER_IMG) * TILE;

    const int p2 = tid & 7;        // pixel pair -> pixels 2*p2, 2*p2+1
    const int g  = tid >> 3;       // 0..31

    const size_t base = (size_t)b * DIMC * PIX_PER_IMG + p0 + 2 * p2;

    // ---- Pass 1: FWHT32 over c_hi; 24 real inputs, 24 needed outputs ----
    {
        uint64_t w[24];
        // ALL loads first: 24 independent LDG.64 -> full MLP
        #pragma unroll
        for (int j = 0; j < 24; j++) {
            const float2 v = __ldcs((const float2*)(x + base +
                               (size_t)(j * 32 + g) * PIX_PER_IMG));
            uint64_t u;
            asm("mov.b64 %0, {%1, %2};" : "=l"(u) : "f"(v.x), "f"(v.y));
            w[j] = u;
        }

        // FWHT8 in place on each 8-block (bits 0..2 of j)
        #pragma unroll
        for (int blk = 0; blk < 3; blk++) {
            uint64_t* u = w + blk * 8;
            #pragma unroll
            for (int st = 0; st < 3; st++) {
                const int m = 1 << st;
                #pragma unroll
                for (int j = 0; j < 8; j++) {
                    if (!(j & m)) {
                        uint64_t a = u[j], c2 = u[j + m];
                        u[j]     = addx2(a, c2);
                        u[j + m] = subx2(a, c2);
                    }
                }
            }
        }

        // H4 (bits 3..4, inputs >= 24 are zero) recombine fused into stores:
        //   t[i]    = a'+b'+c'
        //   t[i+8]  = a'-b'+c'
        //   t[i+16] = a'+b'-c'          (k_hi >= 24 never read downstream)
        #pragma unroll
        for (int i = 0; i < 8; i++) {
            uint64_t A = addx2(w[i], w[i + 8]);
            uint64_t B = subx2(w[i], w[i + 8]);
            s[((i     ) * 33 + g) * 8 + p2] = addx2(A, w[i + 16]);
            s[((i +  8) * 33 + g) * 8 + p2] = addx2(B, w[i + 16]);
            s[((i + 16) * 33 + g) * 8 + p2] = subx2(A, w[i + 16]);
        }
    }
    __syncthreads();

    // ---- Pass 2: FWHT32 over c_lo = stage m=16, then two FWHT16 halves ----
    if (g < 24) {
        const uint64_t SCALE = 0x3D0000003D000000ULL;   // (1/32, 1/32)
        const uint64_t* sr = s + (size_t)g * 33 * 8 + p2;

        #pragma unroll
        for (int half = 0; half < 2; half++) {
            uint64_t u[16];
            if (half == 0) {
                #pragma unroll
                for (int j = 0; j < 16; j++)
                    u[j] = addx2(sr[(size_t)j * 8], sr[(size_t)(j + 16) * 8]);
            } else {
                #pragma unroll
                for (int j = 0; j < 16; j++)
                    u[j] = subx2(sr[(size_t)j * 8], sr[(size_t)(j + 16) * 8]);
            }

            #pragma unroll
            for (int st = 0; st < 4; st++) {
                const int m = 1 << st;
                #pragma unroll
                for (int j = 0; j < 16; j++) {
                    if (!(j & m)) {
                        uint64_t a = u[j], c2 = u[j + m];
                        u[j]     = addx2(a, c2);
                        u[j + m] = subx2(a, c2);
                    }
                }
            }

            #pragma unroll
            for (int k = 0; k < 16; k++) {
                uint64_t r = mulx2(u[k], SCALE);
                float lo, hi;
                asm("mov.b64 {%0, %1}, %2;" : "=f"(lo), "=f"(hi) : "l"(r));
                __stcs((float2*)(y + base +
                        (size_t)(g * 32 + half * 16 + k) * PIX_PER_IMG),
                       make_float2(lo, hi));
            }
        }
    }
}

extern "C" void kernel_launch(void* const* d_in, const int* in_sizes, int n_in,
                              void* d_out, int out_size) {
    (void)in_sizes; (void)n_in; (void)out_size;
    const float* x = (const float*)d_in[0];
    float* y = (float*)d_out;

    const int smem_bytes = 792 * 8 * sizeof(uint64_t);   // 50688
    cudaFuncSetAttribute(fwht1024_kernel,
                         cudaFuncAttributeMaxDynamicSharedMemorySize, smem_bytes);

    const int grid = 16 * TILES_PER_IMG;   // 3136 tiles
    fwht1024_kernel<<<grid, THREADS, smem_bytes>>>(x, y);
}

// round 12
// speedup vs baseline: 1.8270x; 1.2586x over previous
#include <cuda_runtime.h>
#include <cstdint>

// HadamardTransform: y[b,:,h,w] = (H_1024 @ pad(x[b,:,h,w]))[0:768] / 32
// FWHT-1024 per pixel, two register passes over channel bits (5-9 then 0-4),
// packed f32x2 math (2 pixels per thread), 64-bit gmem/smem ops throughout.
// Champion configuration (R5): TILE=16, 256 threads, 3 CTAs/SM, monolithic
// FWHT32 passes, batched loads for full MLP, direct gmem I/O in both passes.

#define DIMC          768
#define TILE          16          // pixels per CTA
#define THREADS       256
#define PIX_PER_IMG   3136        // 56*56
#define TILES_PER_IMG 196         // 3136/16

// ---- packed f32x2 ops (sm_103a) ----
__device__ __forceinline__ uint64_t addx2(uint64_t a, uint64_t b) {
    uint64_t d; asm("add.rn.f32x2 %0, %1, %2;" : "=l"(d) : "l"(a), "l"(b)); return d;
}
__device__ __forceinline__ uint64_t subx2(uint64_t a, uint64_t b) {
    const uint64_t NEG1 = 0xBF800000BF800000ULL;   // (-1.0f, -1.0f)
    uint64_t d; asm("fma.rn.f32x2 %0, %1, %2, %3;" : "=l"(d) : "l"(b), "l"(NEG1), "l"(a)); return d;
}
__device__ __forceinline__ uint64_t mulx2(uint64_t a, uint64_t b) {
    uint64_t d; asm("mul.rn.f32x2 %0, %1, %2;" : "=l"(d) : "l"(a), "l"(b)); return d;
}

// smem layout (float2 units): row r (0..767) at (r + (r>>5))*8 + p2.
// The per-32-row pad makes both passes' 16-lane LDS/STS.64 phases
// conflict-free (32-row stride = 528 words == 16 mod 32).

__global__ __launch_bounds__(THREADS, 3)
void fwht1024_kernel(const float* __restrict__ x, float* __restrict__ y) {
    extern __shared__ uint64_t s[];   // 792*8 = 6336 u64 = 50688 B

    const int tid = threadIdx.x;
    const int T   = blockIdx.x;
    const int b   = T / TILES_PER_IMG;
    const int p0  = (T % TILES_PER_IMG) * TILE;

    const int p2 = tid & 7;        // pixel pair -> pixels 2*p2, 2*p2+1
    const int g  = tid >> 3;       // 0..31

    const size_t base = (size_t)b * DIMC * PIX_PER_IMG + p0 + 2 * p2;

    // ---- Pass 1: butterfly over channel bits 5..9, gmem -> smem ----
    // Thread owns channels c = j*32 + g; j >= 24 are zero padding.
    {
        uint64_t w[32];
        #pragma unroll
        for (int j = 0; j < 24; j++) {
            const float2 v = *(const float2*)(x + base +
                               (size_t)(j * 32 + g) * PIX_PER_IMG);
            uint64_t u;
            asm("mov.b64 %0, {%1, %2};" : "=l"(u) : "f"(v.x), "f"(v.y));
            w[j] = u;
        }
        #pragma unroll
        for (int j = 24; j < 32; j++)
            w[j] = 0ULL;

        #pragma unroll
        for (int st = 0; st < 5; st++) {
            const int m = 1 << st;
            #pragma unroll
            for (int j = 0; j < 32; j++) {
                if (!(j & m)) {
                    uint64_t a = w[j], c2 = w[j + m];
                    w[j]     = addx2(a, c2);
                    w[j + m] = subx2(a, c2);
                }
            }
        }

        // only intermediates with j < 24 are ever read (outputs keep k < 768)
        #pragma unroll
        for (int j = 0; j < 24; j++)
            s[(j * 33 + g) * 8 + p2] = w[j];
    }
    __syncthreads();

    // ---- Pass 2: butterfly over channel bits 0..4, smem -> gmem ----
    if (g < 24) {
        uint64_t w[32];
        #pragma unroll
        for (int j = 0; j < 32; j++)
            w[j] = s[(g * 33 + j) * 8 + p2];

        #pragma unroll
        for (int st = 0; st < 5; st++) {
            const int m = 1 << st;
            #pragma unroll
            for (int j = 0; j < 32; j++) {
                if (!(j & m)) {
                    uint64_t a = w[j], c2 = w[j + m];
                    w[j]     = addx2(a, c2);
                    w[j + m] = subx2(a, c2);
                }
            }
        }

        const uint64_t SCALE = 0x3D0000003D000000ULL;   // (1/32, 1/32)
        #pragma unroll
        for (int j = 0; j < 32; j++) {
            uint64_t r = mulx2(w[j], SCALE);
            float lo, hi;
            asm("mov.b64 {%0, %1}, %2;" : "=f"(lo), "=f"(hi) : "l"(r));
            *(float2*)(y + base + (size_t)(g * 32 + j) * PIX_PER_IMG)
                = make_float2(lo, hi);
        }
    }
}

extern "C" void kernel_launch(void* const* d_in, const int* in_sizes, int n_in,
                              void* d_out, int out_size) {
    (void)in_sizes; (void)n_in; (void)out_size;
    const float* x = (const float*)d_in[0];
    float* y = (float*)d_out;

    const int smem_bytes = 792 * 8 * sizeof(uint64_t);   // 50688
    cudaFuncSetAttribute(fwht1024_kernel,
                         cudaFuncAttributeMaxDynamicSharedMemorySize, smem_bytes);

    const int grid = 16 * TILES_PER_IMG;   // 3136 tiles
    fwht1024_kernel<<<grid, THREADS, smem_bytes>>>(x, y);
}